// round 14
// baseline (speedup 1.0000x reference)
#include <cuda_runtime.h>
#include <cuda_bf16.h>
#include <math_constants.h>

#define C      1000
#define C4     250     // float4 per row
#define NMAT   5
#define THREADS 160    // 5 warps: one warp per matrix
#define PER_LANE 8     // 32 lanes * 8 = 256 >= 250 float4

// ---- monotone encoding of float for atomicMax on unsigned ----
__device__ __forceinline__ unsigned enc_f(float f) {
    unsigned u = __float_as_uint(f);
    return (u & 0x80000000u) ? ~u : (u | 0x80000000u);
}
__device__ __forceinline__ float dec_f(unsigned u) {
    return (u & 0x80000000u) ? __uint_as_float(u & 0x7fffffffu)
                             : __uint_as_float(~u);
}

// Persistent scratch (statically initialized; reset by the last CTA each run
// so every graph replay observes identical initial state).
__device__ unsigned g_max   = 0x007FFFFFu;  // enc(-inf)
__device__ unsigned g_count = 0u;

// combine two (max, 2nd-max) pairs
__device__ __forceinline__ void pair_combine(float& m1, float& m2, float o1, float o2) {
    float n1 = fmaxf(m1, o1);
    float n2 = fmaxf(fminf(m1, o1), fmaxf(m2, o2));
    m1 = n1; m2 = n2;
}

// (max, 2nd-max) of one float4
__device__ __forceinline__ void pair_of4(float4 v, float& p1, float& p2) {
    float hi1 = fmaxf(v.x, v.y), lo1 = fminf(v.x, v.y);
    float hi2 = fmaxf(v.z, v.w), lo2 = fminf(v.z, v.w);
    p1 = fmaxf(hi1, hi2);
    p2 = fmaxf(fminf(hi1, hi2), fmaxf(lo1, lo2));
}

__global__ __launch_bounds__(THREADS)
void margin_kernel(const float* __restrict__ mat0,
                   const float* __restrict__ mat1,
                   const float* __restrict__ mat2,
                   const float* __restrict__ mat3,
                   const float* __restrict__ mat4,
                   const int* __restrict__ targets,   // int32
                   float* __restrict__ out)   // out[0]=max_preds, out[1+row*5 ..]
{
    const int row  = blockIdx.x;
    const int tid  = threadIdx.x;
    const int wid  = tid >> 5;          // 0..4 = matrix index
    const int lane = tid & 31;

    __shared__ float fm1[NMAT];
    __shared__ float fm2[NMAT];
    __shared__ float tv[NMAT];

    // select this warp's matrix pointer (uniform per warp)
    const float* mat = (wid == 0) ? mat0 :
                       (wid == 1) ? mat1 :
                       (wid == 2) ? mat2 :
                       (wid == 3) ? mat3 : mat4;

    const size_t rowoff = (size_t)row * C;
    const float4* rp = (const float4*)(mat + rowoff);

    int t = targets[row];
    t = (t < 0) ? 0 : (t >= C ? C - 1 : t);      // safety clamp

    // --- 8 back-to-back streaming float4 loads per lane (read-once: evict-first) ---
    float4 v[PER_LANE];
#pragma unroll
    for (int k = 0; k < PER_LANE; k++) {
        int idx = lane + k * 32;
        if (idx < C4)
            v[k] = __ldcs(rp + idx);
        else
            v[k] = make_float4(-CUDART_INF_F, -CUDART_INF_F, -CUDART_INF_F, -CUDART_INF_F);
    }

    // --- extract the target logit from registers (no extra LDG):
    //     element t = component (t&3) of float4 (t>>2), held by lane (t>>2)&31
    //     in v[(t>>2)>>5]. t is warp-uniform -> uniform selects + one shuffle.
    {
        const int q    = t >> 2;        // float4 index, 0..249 (always a real load)
        const int k    = q >> 5;        // register index, 0..7 (uniform)
        const int comp = t & 3;         // component (uniform)
        float4 sv = v[0];
#pragma unroll
        for (int kk = 1; kk < PER_LANE; kk++)
            if (k == kk) sv = v[kk];
        float val = (comp == 0) ? sv.x : (comp == 1) ? sv.y : (comp == 2) ? sv.z : sv.w;
        val = __shfl_sync(0xffffffffu, val, q & 31);
        if (lane == 0) tv[wid] = val;
    }

    // serial register-only (max, 2nd-max) fold over 8 float4
    float a1, a2;
    pair_of4(v[0], a1, a2);
#pragma unroll
    for (int k = 1; k < PER_LANE; k++) {
        float p1, p2;
        pair_of4(v[k], p1, p2);
        pair_combine(a1, a2, p1, p2);
    }

    // single 5-level warp shuffle tree
#pragma unroll
    for (int off = 16; off; off >>= 1) {
        float o1 = __shfl_xor_sync(0xffffffffu, a1, off);
        float o2 = __shfl_xor_sync(0xffffffffu, a2, off);
        pair_combine(a1, a2, o1, o2);
    }

    if (lane == 0) { fm1[wid] = a1; fm2[wid] = a2; }
    __syncthreads();

    if (tid == 0) {
        // margins and 5-way softmax (T = 2)
        float mg[NMAT];
        float mx = -CUDART_INF_F;
#pragma unroll
        for (int j = 0; j < NMAT; j++) {
            float m = (tv[j] == fm1[j]) ? (fm1[j] - fm2[j]) * 0.5f : 0.0f;
            mg[j] = m;
            mx = fmaxf(mx, m);
        }
        float e[NMAT], s = 0.0f;
#pragma unroll
        for (int j = 0; j < NMAT; j++) { e[j] = __expf(mg[j] - mx); s += e[j]; }
        float inv = 1.0f / s;
        float* o = out + 1 + (size_t)row * NMAT;
#pragma unroll
        for (int j = 0; j < NMAT; j++) o[j] = e[j] * inv;

        // global max over the first 4 matrices (order-independent -> deterministic)
        float gmax = fmaxf(fmaxf(fm1[0], fm1[1]), fmaxf(fm1[2], fm1[3]));
        atomicMax(&g_max, enc_f(gmax));
        __threadfence();
        unsigned ticket = atomicAdd(&g_count, 1u);
        if (ticket == gridDim.x - 1) {
            // all CTAs' atomicMax are fenced before their ticket -> g_max final
            unsigned u = atomicOr(&g_max, 0u);
            out[0] = dec_f(u);
            // reset scratch for the next (graph-replayed) execution
            atomicExch(&g_max, 0x007FFFFFu);
            atomicExch(&g_count, 0u);
        }
    }
}

extern "C" void kernel_launch(void* const* d_in, const int* in_sizes, int n_in,
                              void* d_out, int out_size)
{
    // Classify inputs by element count: 5 largest equal-size buffers = matrices
    // (in order of appearance: outputs1..4, mimic); size == S/C = targets (int32).
    // Scalars (n_test) ignored.
    long long S = 0;
    for (int i = 0; i < n_in; i++)
        if ((long long)in_sizes[i] > S) S = in_sizes[i];

    const float* mats[NMAT] = {0, 0, 0, 0, 0};
    const int*   targets = 0;
    int nm = 0;
    for (int i = 0; i < n_in; i++) {
        if ((long long)in_sizes[i] == S && nm < NMAT) {
            mats[nm++] = (const float*)d_in[i];
        } else if ((long long)in_sizes[i] == S / C) {
            targets = (const int*)d_in[i];
        }
    }

    const int N = (int)(S / C);
    float* out = (float*)d_out;

    if (nm != NMAT || targets == 0 || N <= 0) return;  // classification failed: do nothing

    margin_kernel<<<N, THREADS>>>(mats[0], mats[1], mats[2], mats[3], mats[4],
                                  targets, out);
}

// round 15
// speedup vs baseline: 1.1230x; 1.1230x over previous
#include <cuda_runtime.h>
#include <cuda_bf16.h>
#include <math_constants.h>

#define C      1000
#define C4     250     // float4 per row
#define NMAT   5
#define THREADS 160    // 5 warps: one warp per matrix
#define PER_LANE 8     // 32 lanes * 8 = 256 >= 250 float4

// ---- monotone encoding of float for atomicMax on unsigned ----
__device__ __forceinline__ unsigned enc_f(float f) {
    unsigned u = __float_as_uint(f);
    return (u & 0x80000000u) ? ~u : (u | 0x80000000u);
}
__device__ __forceinline__ float dec_f(unsigned u) {
    return (u & 0x80000000u) ? __uint_as_float(u & 0x7fffffffu)
                             : __uint_as_float(~u);
}

// Persistent scratch (statically initialized; reset by the last CTA each run
// so every graph replay observes identical initial state).
__device__ unsigned g_max   = 0x007FFFFFu;  // enc(-inf)
__device__ unsigned g_count = 0u;

// combine two (max, 2nd-max) pairs
__device__ __forceinline__ void pair_combine(float& m1, float& m2, float o1, float o2) {
    float n1 = fmaxf(m1, o1);
    float n2 = fmaxf(fminf(m1, o1), fmaxf(m2, o2));
    m1 = n1; m2 = n2;
}

// (max, 2nd-max) of one float4
__device__ __forceinline__ void pair_of4(float4 v, float& p1, float& p2) {
    float hi1 = fmaxf(v.x, v.y), lo1 = fminf(v.x, v.y);
    float hi2 = fmaxf(v.z, v.w), lo2 = fminf(v.z, v.w);
    p1 = fmaxf(hi1, hi2);
    p2 = fmaxf(fminf(hi1, hi2), fmaxf(lo1, lo2));
}

__global__ __launch_bounds__(THREADS)
void margin_kernel(const float* __restrict__ mat0,
                   const float* __restrict__ mat1,
                   const float* __restrict__ mat2,
                   const float* __restrict__ mat3,
                   const float* __restrict__ mat4,
                   const int* __restrict__ targets,   // int32
                   float* __restrict__ out)   // out[0]=max_preds, out[1+row*5 ..]
{
    const int row  = blockIdx.x;
    const int tid  = threadIdx.x;
    const int wid  = tid >> 5;          // 0..4 = matrix index
    const int lane = tid & 31;

    __shared__ float fm1[NMAT];
    __shared__ float fm2[NMAT];
    __shared__ float tv[NMAT];

    // select this warp's matrix pointer (uniform per warp -> SEL chain, no lmem)
    const float* mat = (wid == 0) ? mat0 :
                       (wid == 1) ? mat1 :
                       (wid == 2) ? mat2 :
                       (wid == 3) ? mat3 : mat4;

    const size_t rowoff = (size_t)row * C;
    const float4* rp = (const float4*)(mat + rowoff);

    int t = targets[row];
    t = (t < 0) ? 0 : (t >= C ? C - 1 : t);      // safety clamp
    if (lane == 0)
        tv[wid] = __ldg(mat + rowoff + (size_t)t);

    // --- 8 back-to-back streaming float4 loads per lane (read-once: evict-first) ---
    float4 v[PER_LANE];
#pragma unroll
    for (int k = 0; k < PER_LANE; k++) {
        int idx = lane + k * 32;
        if (idx < C4)
            v[k] = __ldcs(rp + idx);
        else
            v[k] = make_float4(-CUDART_INF_F, -CUDART_INF_F, -CUDART_INF_F, -CUDART_INF_F);
    }

    // serial register-only (max, 2nd-max) fold over 8 float4
    float a1, a2;
    pair_of4(v[0], a1, a2);
#pragma unroll
    for (int k = 1; k < PER_LANE; k++) {
        float p1, p2;
        pair_of4(v[k], p1, p2);
        pair_combine(a1, a2, p1, p2);
    }

    // single 5-level warp shuffle tree
#pragma unroll
    for (int off = 16; off; off >>= 1) {
        float o1 = __shfl_xor_sync(0xffffffffu, a1, off);
        float o2 = __shfl_xor_sync(0xffffffffu, a2, off);
        pair_combine(a1, a2, o1, o2);
    }

    if (lane == 0) { fm1[wid] = a1; fm2[wid] = a2; }
    __syncthreads();

    if (tid == 0) {
        // margins and 5-way softmax (T = 2)
        float mg[NMAT];
        float mx = -CUDART_INF_F;
#pragma unroll
        for (int j = 0; j < NMAT; j++) {
            float m = (tv[j] == fm1[j]) ? (fm1[j] - fm2[j]) * 0.5f : 0.0f;
            mg[j] = m;
            mx = fmaxf(mx, m);
        }
        float e[NMAT], s = 0.0f;
#pragma unroll
        for (int j = 0; j < NMAT; j++) { e[j] = __expf(mg[j] - mx); s += e[j]; }
        float inv = 1.0f / s;
        float* o = out + 1 + (size_t)row * NMAT;
#pragma unroll
        for (int j = 0; j < NMAT; j++) o[j] = e[j] * inv;

        // global max over the first 4 matrices (order-independent -> deterministic)
        float gmax = fmaxf(fmaxf(fm1[0], fm1[1]), fmaxf(fm1[2], fm1[3]));
        atomicMax(&g_max, enc_f(gmax));
        __threadfence();
        unsigned ticket = atomicAdd(&g_count, 1u);
        if (ticket == gridDim.x - 1) {
            // all CTAs' atomicMax are fenced before their ticket -> g_max final
            unsigned u = atomicOr(&g_max, 0u);
            out[0] = dec_f(u);
            // reset scratch for the next (graph-replayed) execution
            atomicExch(&g_max, 0x007FFFFFu);
            atomicExch(&g_count, 0u);
        }
    }
}

extern "C" void kernel_launch(void* const* d_in, const int* in_sizes, int n_in,
                              void* d_out, int out_size)
{
    // Classify inputs by element count: 5 largest equal-size buffers = matrices
    // (in order of appearance: outputs1..4, mimic); size == S/C = targets (int32).
    // Scalars (n_test) ignored.
    long long S = 0;
    for (int i = 0; i < n_in; i++)
        if ((long long)in_sizes[i] > S) S = in_sizes[i];

    const float* mats[NMAT] = {0, 0, 0, 0, 0};
    const int*   targets = 0;
    int nm = 0;
    for (int i = 0; i < n_in; i++) {
        if ((long long)in_sizes[i] == S && nm < NMAT) {
            mats[nm++] = (const float*)d_in[i];
        } else if ((long long)in_sizes[i] == S / C) {
            targets = (const int*)d_in[i];
        }
    }

    const int N = (int)(S / C);
    float* out = (float*)d_out;

    if (nm != NMAT || targets == 0 || N <= 0) return;  // classification failed: do nothing

    margin_kernel<<<N, THREADS>>>(mats[0], mats[1], mats[2], mats[3], mats[4],
                                  targets, out);
}